// round 4
// baseline (speedup 1.0000x reference)
#include <cuda_runtime.h>
#include <cstdint>

// ---------------------------------------------------------------------------
// RejectionSampler: chain speculative sampling, flashinfer-style.
// Reproduces JAX threefry2x32 PARTITIONABLE RNG streams bit-exactly
// (jax_threefry_partitionable=True, the modern default):
//   split(key,3):  key_i = threefry2x32(key, 0, i)           (full pair)
//   random_bits32: bits_j = o0 ^ o1 of threefry2x32(key, 0, j)
// Streams:
//   u       = uniform(ku, (B,N))    -> accept test
//   gumbelR = gumbel(kr, (B,N,V))   -> recovered argmax
//   gumbelB = gumbel(kb, (B,V))     -> bonus argmax
// argmax(log(x+EPS)+gumbel) computed as argmax x / (-log u)  (monotone).
// Output FLOAT32: [ (B,N+1) tokens | (B,) accepted | (B,) emitted ]
// ---------------------------------------------------------------------------

#define B_  64
#define N_  8
#define V_  128000
#define ROWS (B_ * N_)              // 512
#define SPLITS_R 32
#define SPLITS_B 16
#define THREADS_R 256
#define TINY_F 1.17549435e-38f

// scratch (no allocations allowed)
__device__ float g_rval[ROWS * SPLITS_R];
__device__ int   g_ridx[ROWS * SPLITS_R];
__device__ float g_bval[B_ * SPLITS_B];
__device__ int   g_bidx[B_ * SPLITS_B];

// ---------------- threefry2x32 (JAX-compatible) ----------------
__host__ __device__ __forceinline__ void threefry2x32(
    uint32_t k0, uint32_t k1, uint32_t x0, uint32_t x1,
    uint32_t* y0, uint32_t* y1)
{
    uint32_t k2 = k0 ^ k1 ^ 0x1BD11BDAu;
    x0 += k0; x1 += k1;
#ifdef __CUDA_ARCH__
#define ROTL32(v, r) __funnelshift_l((v), (v), (r))
#else
#define ROTL32(v, r) (((v) << (r)) | ((v) >> (32 - (r))))
#endif
#define TF_RND(r) { x0 += x1; x1 = ROTL32(x1, r); x1 ^= x0; }
    TF_RND(13) TF_RND(15) TF_RND(26) TF_RND(6)   x0 += k1; x1 += k2 + 1u;
    TF_RND(17) TF_RND(29) TF_RND(16) TF_RND(24)  x0 += k2; x1 += k0 + 2u;
    TF_RND(13) TF_RND(15) TF_RND(26) TF_RND(6)   x0 += k0; x1 += k1 + 3u;
    TF_RND(17) TF_RND(29) TF_RND(16) TF_RND(24)  x0 += k1; x1 += k2 + 4u;
    TF_RND(13) TF_RND(15) TF_RND(26) TF_RND(6)   x0 += k2; x1 += k0 + 5u;
#undef TF_RND
#undef ROTL32
    *y0 = x0; *y1 = x1;
}

// partitionable 32-bit draw: counter (0, j), output o0 ^ o1
__device__ __forceinline__ uint32_t tf_bits32(uint32_t k0, uint32_t k1, uint32_t j) {
    uint32_t o0, o1;
    threefry2x32(k0, k1, 0u, j, &o0, &o1);
    return o0 ^ o1;
}

// bits -> uniform [0,1) exactly as JAX
__device__ __forceinline__ float bits_to_u(uint32_t bits) {
    return __uint_as_float((bits >> 9) | 0x3f800000u) - 1.0f;
}
// bits -> E = -log(u') with u' = (u==0 ? tiny : u)   (gumbel path)
__device__ __forceinline__ float bits_to_E(uint32_t bits) {
    float u = bits_to_u(bits);
    if (u == 0.0f) u = TINY_F;
    return -__logf(u);
}

// block argmax reduction with first-index tie-break
__device__ __forceinline__ void block_argmax(
    float v, int i, float* sv, int* si, float* outv, int* outi)
{
    int t = threadIdx.x;
    sv[t] = v; si[t] = i;
    __syncthreads();
    for (int o = blockDim.x >> 1; o > 0; o >>= 1) {
        if (t < o) {
            float v2 = sv[t + o]; int i2 = si[t + o];
            if (v2 > sv[t] || (v2 == sv[t] && i2 < si[t])) { sv[t] = v2; si[t] = i2; }
        }
        __syncthreads();
    }
    if (t == 0) { *outv = sv[0]; *outi = si[0]; }
}

// ---------------- kernel 1: recovered partial argmax ----------------
// block = (row, split). score_v = max(verify - draft, 0) / (-log u_v),
// u_v from bits at counter j = row*V + v under key kr.
__global__ __launch_bounds__(THREADS_R)
void recovered_partial_kernel(const float* __restrict__ verify,
                              const float* __restrict__ draft,
                              uint32_t kr0, uint32_t kr1)
{
    __shared__ float sv[THREADS_R];
    __shared__ int   si[THREADS_R];

    const int row = blockIdx.x / SPLITS_R;      // 0..511
    const int s   = blockIdx.x % SPLITS_R;
    const long vOff = ((long)(row >> 3) * 9 + (row & 7)) * V_;
    const long dOff = (long)row * V_;

    const int chunk = V_ / SPLITS_R;            // 4000
    const int v0 = s * chunk;

    const float4* vr4 = (const float4*)(verify + vOff + v0);
    const float4* dr4 = (const float4*)(draft  + dOff + v0);

    float bv = -1.0f;
    int   bi = v0;

    const int n4 = chunk / 4;                   // 1000
    for (int q = threadIdx.x; q < n4; q += THREADS_R) {
        float4 va = vr4[q], da = dr4[q];
        int vbase = v0 + q * 4;
        uint32_t cbase = (uint32_t)row * (uint32_t)V_ + (uint32_t)vbase;
        float r[4] = { va.x - da.x, va.y - da.y, va.z - da.z, va.w - da.w };
#pragma unroll
        for (int j = 0; j < 4; j++) {
            uint32_t bits = tf_bits32(kr0, kr1, cbase + j);
            float E = bits_to_E(bits);
            float f = r[j] > 0.0f ? __fdividef(r[j], E) : 0.0f;
            if (f > bv) { bv = f; bi = vbase + j; }
        }
    }

    block_argmax(bv, bi, sv, si, &g_rval[row * SPLITS_R + s], &g_ridx[row * SPLITS_R + s]);
}

// ---------------- kernel 2: bonus partial argmax ----------------
// rows = verify[:, N, :]; bits at counter j = b*V + v under key kb.
__global__ __launch_bounds__(THREADS_R)
void bonus_partial_kernel(const float* __restrict__ verify,
                          uint32_t kb0, uint32_t kb1)
{
    __shared__ float sv[THREADS_R];
    __shared__ int   si[THREADS_R];

    const int b = blockIdx.x / SPLITS_B;        // 0..63
    const int s = blockIdx.x % SPLITS_B;
    const long vOff = ((long)b * 9 + 8) * V_;

    const int chunk = V_ / SPLITS_B;            // 8000
    const int v0 = s * chunk;

    const float4* p4 = (const float4*)(verify + vOff + v0);

    float bv = -1.0f;
    int   bi = v0;

    const int n4 = chunk / 4;                   // 2000
    for (int q = threadIdx.x; q < n4; q += THREADS_R) {
        float4 pa = p4[q];
        int vbase = v0 + q * 4;
        uint32_t cbase = (uint32_t)b * (uint32_t)V_ + (uint32_t)vbase;
        float f[4] = { pa.x, pa.y, pa.z, pa.w };
#pragma unroll
        for (int j = 0; j < 4; j++) {
            uint32_t bits = tf_bits32(kb0, kb1, cbase + j);
            float sc = __fdividef(f[j], bits_to_E(bits));
            if (sc > bv) { bv = sc; bi = vbase + j; }
        }
    }

    block_argmax(bv, bi, sv, si, &g_bval[b * SPLITS_B + s], &g_bidx[b * SPLITS_B + s]);
}

// ---------------- kernel 3: finalize ----------------
__global__ __launch_bounds__(512)
void finalize_kernel(const int* __restrict__ ids,
                     const float* __restrict__ verify,
                     const float* __restrict__ draft,
                     uint32_t ku0, uint32_t ku1,
                     float* __restrict__ out)
{
    __shared__ float su[ROWS];
    __shared__ int   rec[ROWS];
    __shared__ int   bon[B_];
    const int t = threadIdx.x;

    // accept uniforms: partitionable bits at counter j, key ku
    su[t] = bits_to_u(tf_bits32(ku0, ku1, (uint32_t)t));

    // reduce recovered partials (one thread per row)
    {
        float bv = -2.0f; int bi = 0;
        for (int s = 0; s < SPLITS_R; s++) {
            float v = g_rval[t * SPLITS_R + s];
            int   i = g_ridx[t * SPLITS_R + s];
            if (v > bv || (v == bv && i < bi)) { bv = v; bi = i; }
        }
        rec[t] = bi;
    }
    if (t < B_) {
        float bv = -2.0f; int bi = 0;
        for (int s = 0; s < SPLITS_B; s++) {
            float v = g_bval[t * SPLITS_B + s];
            int   i = g_bidx[t * SPLITS_B + s];
            if (v > bv || (v == bv && i < bi)) { bv = v; bi = i; }
        }
        bon[t] = bi;
    }
    __syncthreads();

    if (t < B_) {
        const int b = t;
        int acc = 0, emitted = 0;
        bool chain = true;
        for (int n = 0; n < N_; n++) {
            int idx = b * N_ + n;
            int tok = ids[idx];
            float p = verify[((long)b * 9 + n) * V_ + tok];
            float q = draft[(long)idx * V_ + tok];
            float u = su[idx];
            bool a = __fmul_rn(u, q) < p;
            acc += a ? 1 : 0;
            if (chain) { if (a) emitted++; else chain = false; }
        }
        int final_tok = (emitted < N_) ? rec[b * N_ + emitted] : bon[b];
        for (int i = 0; i <= N_; i++) {
            float val;
            if (i < emitted)       val = (float)ids[b * N_ + i];
            else if (i == emitted) val = (float)final_tok;
            else                   val = -1.0f;
            out[b * (N_ + 1) + i] = val;
        }
        out[B_ * (N_ + 1) + b]       = (float)acc;      // accepted_token_num
        out[B_ * (N_ + 1) + B_ + b]  = (float)emitted;  // emitted_token_num
    }
}

// ---------------- host launch ----------------
extern "C" void kernel_launch(void* const* d_in, const int* in_sizes, int n_in,
                              void* d_out, int out_size)
{
    // Bind inputs BY ELEMENT COUNT:
    //   512         -> draft_token_ids (int32)
    //   65,536,000  -> draft_probs   (B*N*V)
    //   73,728,000  -> verify_probs  (B*(N+1)*V)
    const int*   draft_ids = nullptr;
    const float* draft_p   = nullptr;
    const float* verify_p  = nullptr;
    for (int i = 0; i < n_in; i++) {
        long sz = in_sizes[i];
        if (sz == (long)ROWS)                 draft_ids = (const int*)d_in[i];
        else if (sz == (long)B_ * N_ * V_)    draft_p   = (const float*)d_in[i];
        else if (sz == (long)B_ * 9 * V_)     verify_p  = (const float*)d_in[i];
    }
    float* out = (float*)d_out;

    // key(1) = (0, 1); split(key, 3) FOLD-LIKE (partitionable):
    //   key_i = threefry2x32(key, 0, i)
    uint32_t ku0, ku1, kr0, kr1, kb0, kb1;
    threefry2x32(0u, 1u, 0u, 0u, &ku0, &ku1);
    threefry2x32(0u, 1u, 0u, 1u, &kr0, &kr1);
    threefry2x32(0u, 1u, 0u, 2u, &kb0, &kb1);

    recovered_partial_kernel<<<ROWS * SPLITS_R, THREADS_R>>>(verify_p, draft_p, kr0, kr1);
    bonus_partial_kernel<<<B_ * SPLITS_B, THREADS_R>>>(verify_p, kb0, kb1);
    finalize_kernel<<<1, 512>>>(draft_ids, verify_p, draft_p, ku0, ku1, out);
}

// round 6
// speedup vs baseline: 1.3136x; 1.3136x over previous
#include <cuda_runtime.h>
#include <cstdint>

// ---------------------------------------------------------------------------
// RejectionSampler: chain speculative sampling, flashinfer-style.
// JAX threefry2x32 PARTITIONABLE streams (bit-exact, verified rel_err=0.0):
//   split(key,3):  key_i = threefry2x32(key, 0, i)
//   random_bits32: bits_j = o0 ^ o1 of threefry2x32(key, 0, j)
// argmax(log(x+EPS)+gumbel) computed as argmax x / (-log u)  (monotone).
// R6: warp-ballot compaction with UNIFORM loop trip count (fixes R5 hang:
//     125 float4/warp is not a multiple of 32, so the tail iteration ran
//     __ballot_sync with divergent lanes -> deadlock).
// Output FLOAT32: [ (B,N+1) tokens | (B,) accepted | (B,) emitted ]
// ---------------------------------------------------------------------------

#define B_  64
#define N_  8
#define V_  128000
#define ROWS (B_ * N_)              // 512
#define SPLITS_R 32
#define SPLITS_B 16
#define THREADS_R 256
#define WARPS_R (THREADS_R / 32)    // 8
#define CHUNK_R (V_ / SPLITS_R)     // 4000 elements per block
#define WCHUNK  (CHUNK_R / WARPS_R) // 500 elements per warp
#define WCHUNK4 (WCHUNK / 4)        // 125 float4 per warp
#define WITERS  ((WCHUNK4 + 31) / 32) // 4 uniform iterations
#define GRID_REC (ROWS * SPLITS_R)  // 16384
#define GRID_BON (B_ * SPLITS_B)    // 1024
#define TINY_F 1.17549435e-38f

// scratch (no allocations allowed)
__device__ float g_rval[ROWS * SPLITS_R];
__device__ int   g_ridx[ROWS * SPLITS_R];
__device__ float g_bval[B_ * SPLITS_B];
__device__ int   g_bidx[B_ * SPLITS_B];

// ---------------- threefry2x32 (JAX-compatible) ----------------
__host__ __device__ __forceinline__ void threefry2x32(
    uint32_t k0, uint32_t k1, uint32_t x0, uint32_t x1,
    uint32_t* y0, uint32_t* y1)
{
    uint32_t k2 = k0 ^ k1 ^ 0x1BD11BDAu;
    x0 += k0; x1 += k1;
#ifdef __CUDA_ARCH__
#define ROTL32(v, r) __funnelshift_l((v), (v), (r))
#else
#define ROTL32(v, r) (((v) << (r)) | ((v) >> (32 - (r))))
#endif
#define TF_RND(r) { x0 += x1; x1 = ROTL32(x1, r); x1 ^= x0; }
    TF_RND(13) TF_RND(15) TF_RND(26) TF_RND(6)   x0 += k1; x1 += k2 + 1u;
    TF_RND(17) TF_RND(29) TF_RND(16) TF_RND(24)  x0 += k2; x1 += k0 + 2u;
    TF_RND(13) TF_RND(15) TF_RND(26) TF_RND(6)   x0 += k0; x1 += k1 + 3u;
    TF_RND(17) TF_RND(29) TF_RND(16) TF_RND(24)  x0 += k1; x1 += k2 + 4u;
    TF_RND(13) TF_RND(15) TF_RND(26) TF_RND(6)   x0 += k2; x1 += k0 + 5u;
#undef TF_RND
#undef ROTL32
    *y0 = x0; *y1 = x1;
}

// partitionable 32-bit draw: counter (0, j), output o0 ^ o1
__device__ __forceinline__ uint32_t tf_bits32(uint32_t k0, uint32_t k1, uint32_t j) {
    uint32_t o0, o1;
    threefry2x32(k0, k1, 0u, j, &o0, &o1);
    return o0 ^ o1;
}

// bits -> uniform [0,1) exactly as JAX
__device__ __forceinline__ float bits_to_u(uint32_t bits) {
    return __uint_as_float((bits >> 9) | 0x3f800000u) - 1.0f;
}
// bits -> E = -log(u') with u' = (u==0 ? tiny : u)
__device__ __forceinline__ float bits_to_E(uint32_t bits) {
    float u = bits_to_u(bits);
    if (u == 0.0f) u = TINY_F;
    return -__logf(u);
}

// block argmax reduction with first-index tie-break
__device__ __forceinline__ void block_argmax(
    float v, int i, float* sv, int* si, float* outv, int* outi)
{
    int t = threadIdx.x;
    sv[t] = v; si[t] = i;
    __syncthreads();
    for (int o = blockDim.x >> 1; o > 0; o >>= 1) {
        if (t < o) {
            float v2 = sv[t + o]; int i2 = si[t + o];
            if (v2 > sv[t] || (v2 == sv[t] && i2 < si[t])) { sv[t] = v2; si[t] = i2; }
        }
        __syncthreads();
    }
    if (t == 0) { *outv = sv[0]; *outi = si[0]; }
}

// ---------------- fused partial-argmax kernel ----------------
// blocks [0, GRID_REC): recovered residual argmax with warp compaction
// blocks [GRID_REC, GRID_REC+GRID_BON): bonus argmax (all elements need RNG)
__global__ __launch_bounds__(THREADS_R)
void partial_kernel(const float* __restrict__ verify,
                    const float* __restrict__ draft,
                    uint32_t kr0, uint32_t kr1,
                    uint32_t kb0, uint32_t kb1)
{
    __shared__ float sv[THREADS_R];
    __shared__ int   si[THREADS_R];

    const int t    = threadIdx.x;
    const int lane = t & 31;
    const int warp = t >> 5;

    if (blockIdx.x < GRID_REC) {
        // ---- recovered: compaction ----
        __shared__ float rbuf[WARPS_R][WCHUNK];
        __shared__ int   ibuf[WARPS_R][WCHUNK];

        const int row = blockIdx.x / SPLITS_R;      // 0..511
        const int s   = blockIdx.x % SPLITS_R;
        const long vOff = ((long)(row >> 3) * 9 + (row & 7)) * V_;
        const long dOff = (long)row * V_;
        const int v0 = s * CHUNK_R;

        const float4* vr4 = (const float4*)(verify + vOff + v0);
        const float4* dr4 = (const float4*)(draft  + dOff + v0);

        // Phase A: stream residuals, compact positives into warp buffer.
        // UNIFORM trip count: every lane executes every iteration; lanes past
        // the end carry valid=false (ballot-safe).
        const int qbase = warp * WCHUNK4;
        int cnt = 0;                                 // warp-uniform count
#pragma unroll
        for (int it = 0; it < WITERS; it++) {
            int qi = it * 32 + lane;                 // 0..127
            bool valid = qi < WCHUNK4;
            int q = qbase + (valid ? qi : 0);        // clamp: safe dummy load
            float4 va = vr4[q], da = dr4[q];
            float r[4] = { va.x - da.x, va.y - da.y, va.z - da.z, va.w - da.w };
            int ebase = v0 + q * 4;
#pragma unroll
            for (int j = 0; j < 4; j++) {
                bool pos = valid && (r[j] > 0.0f);
                unsigned m = __ballot_sync(0xFFFFFFFFu, pos);
                if (pos) {
                    int slot = cnt + __popc(m & ((1u << lane) - 1u));
                    rbuf[warp][slot] = r[j];
                    ibuf[warp][slot] = ebase + j;
                }
                cnt += __popc(m);
            }
        }
        __syncwarp();

        // Phase B: threefry only for compacted positives
        float bv = -1.0f;
        int   bi = v0;
        const uint32_t rowbase = (uint32_t)row * (uint32_t)V_;
        for (int k = lane; k < cnt; k += 32) {
            float r  = rbuf[warp][k];
            int   ix = ibuf[warp][k];
            uint32_t bits = tf_bits32(kr0, kr1, rowbase + (uint32_t)ix);
            float f = __fdividef(r, bits_to_E(bits));
            if (f > bv) { bv = f; bi = ix; }
        }

        block_argmax(bv, bi, sv, si,
                     &g_rval[row * SPLITS_R + s], &g_ridx[row * SPLITS_R + s]);
    } else {
        // ---- bonus: all elements ----
        const int bid = blockIdx.x - GRID_REC;
        const int b = bid / SPLITS_B;               // 0..63
        const int s = bid % SPLITS_B;
        const long vOff = ((long)b * 9 + 8) * V_;

        const int chunk = V_ / SPLITS_B;            // 8000
        const int v0 = s * chunk;
        const float4* p4 = (const float4*)(verify + vOff + v0);

        float bv = -1.0f;
        int   bi = v0;

        const int n4 = chunk / 4;                   // 2000
        for (int q = t; q < n4; q += THREADS_R) {
            float4 pa = p4[q];
            int vbase = v0 + q * 4;
            uint32_t cbase = (uint32_t)b * (uint32_t)V_ + (uint32_t)vbase;
            float f[4] = { pa.x, pa.y, pa.z, pa.w };
#pragma unroll
            for (int j = 0; j < 4; j++) {
                uint32_t bits = tf_bits32(kb0, kb1, cbase + j);
                float sc = __fdividef(f[j], bits_to_E(bits));
                if (sc > bv) { bv = sc; bi = vbase + j; }
            }
        }

        block_argmax(bv, bi, sv, si,
                     &g_bval[b * SPLITS_B + s], &g_bidx[b * SPLITS_B + s]);
    }
}

// ---------------- finalize ----------------
__global__ __launch_bounds__(512)
void finalize_kernel(const int* __restrict__ ids,
                     const float* __restrict__ verify,
                     const float* __restrict__ draft,
                     uint32_t ku0, uint32_t ku1,
                     float* __restrict__ out)
{
    __shared__ float su[ROWS];
    __shared__ int   rec[ROWS];
    __shared__ int   bon[B_];
    const int t = threadIdx.x;

    su[t] = bits_to_u(tf_bits32(ku0, ku1, (uint32_t)t));

    {
        float bv = -2.0f; int bi = 0;
        for (int s = 0; s < SPLITS_R; s++) {
            float v = g_rval[t * SPLITS_R + s];
            int   i = g_ridx[t * SPLITS_R + s];
            if (v > bv || (v == bv && i < bi)) { bv = v; bi = i; }
        }
        rec[t] = bi;
    }
    if (t < B_) {
        float bv = -2.0f; int bi = 0;
        for (int s = 0; s < SPLITS_B; s++) {
            float v = g_bval[t * SPLITS_B + s];
            int   i = g_bidx[t * SPLITS_B + s];
            if (v > bv || (v == bv && i < bi)) { bv = v; bi = i; }
        }
        bon[t] = bi;
    }
    __syncthreads();

    if (t < B_) {
        const int b = t;
        int acc = 0, emitted = 0;
        bool chain = true;
        for (int n = 0; n < N_; n++) {
            int idx = b * N_ + n;
            int tok = ids[idx];
            float p = verify[((long)b * 9 + n) * V_ + tok];
            float q = draft[(long)idx * V_ + tok];
            float u = su[idx];
            bool a = __fmul_rn(u, q) < p;
            acc += a ? 1 : 0;
            if (chain) { if (a) emitted++; else chain = false; }
        }
        int final_tok = (emitted < N_) ? rec[b * N_ + emitted] : bon[b];
        for (int i = 0; i <= N_; i++) {
            float val;
            if (i < emitted)       val = (float)ids[b * N_ + i];
            else if (i == emitted) val = (float)final_tok;
            else                   val = -1.0f;
            out[b * (N_ + 1) + i] = val;
        }
        out[B_ * (N_ + 1) + b]       = (float)acc;      // accepted_token_num
        out[B_ * (N_ + 1) + B_ + b]  = (float)emitted;  // emitted_token_num
    }
}

// ---------------- host launch ----------------
extern "C" void kernel_launch(void* const* d_in, const int* in_sizes, int n_in,
                              void* d_out, int out_size)
{
    // Bind inputs BY ELEMENT COUNT:
    const int*   draft_ids = nullptr;
    const float* draft_p   = nullptr;
    const float* verify_p  = nullptr;
    for (int i = 0; i < n_in; i++) {
        long sz = in_sizes[i];
        if (sz == (long)ROWS)                 draft_ids = (const int*)d_in[i];
        else if (sz == (long)B_ * N_ * V_)    draft_p   = (const float*)d_in[i];
        else if (sz == (long)B_ * 9 * V_)     verify_p  = (const float*)d_in[i];
    }
    float* out = (float*)d_out;

    // key(1) = (0, 1); split(key, 3) fold-like (partitionable)
    uint32_t ku0, ku1, kr0, kr1, kb0, kb1;
    threefry2x32(0u, 1u, 0u, 0u, &ku0, &ku1);
    threefry2x32(0u, 1u, 0u, 1u, &kr0, &kr1);
    threefry2x32(0u, 1u, 0u, 2u, &kb0, &kb1);

    partial_kernel<<<GRID_REC + GRID_BON, THREADS_R>>>(
        verify_p, draft_p, kr0, kr1, kb0, kb1);
    finalize_kernel<<<1, 512>>>(draft_ids, verify_p, draft_p, ku0, ku1, out);
}

// round 7
// speedup vs baseline: 1.3258x; 1.0093x over previous
#include <cuda_runtime.h>
#include <cstdint>

// ---------------------------------------------------------------------------
// RejectionSampler: chain speculative sampling, flashinfer-style.
// JAX threefry2x32 PARTITIONABLE streams (bit-exact, verified rel_err=0.0):
//   split(key,3):  key_i = threefry2x32(key, 0, i)
//   random_bits32: bits_j = o0 ^ o1 of threefry2x32(key, 0, j)
// argmax(log(x+EPS)+gumbel) computed as argmax x / (-log u)  (monotone).
// R7: single fused kernel.
//   - warp-ballot compaction drained in 2 halves (256-entry buffers) so smem
//     fits 8 blocks/SM; __launch_bounds__(256,8) forces 32 regs -> 64 warps/SM
//   - finalize runs in the LAST block (atomic done-counter + threadfence),
//     removing the serialized 28us 1-block tail kernel
// Output FLOAT32: [ (B,N+1) tokens | (B,) accepted | (B,) emitted ]
// ---------------------------------------------------------------------------

#define B_  64
#define N_  8
#define V_  128000
#define ROWS (B_ * N_)              // 512
#define SPLITS_R 32
#define SPLITS_B 16
#define THREADS_R 256
#define WARPS_R (THREADS_R / 32)    // 8
#define CHUNK_R (V_ / SPLITS_R)     // 4000 elements per block
#define WCHUNK4 ((CHUNK_R / WARPS_R) / 4) // 125 float4 per warp
#define GRID_REC (ROWS * SPLITS_R)  // 16384
#define GRID_BON (B_ * SPLITS_B)    // 1024
#define GRID_TOT (GRID_REC + GRID_BON)
#define CAP 256                     // per-warp compaction buffer (per half)
#define TINY_F 1.17549435e-38f

// scratch (no allocations allowed)
__device__ float g_rval[ROWS * SPLITS_R];
__device__ int   g_ridx[ROWS * SPLITS_R];
__device__ float g_bval[B_ * SPLITS_B];
__device__ int   g_bidx[B_ * SPLITS_B];
__device__ unsigned g_done = 0;

// ---------------- threefry2x32 (JAX-compatible) ----------------
__host__ __device__ __forceinline__ void threefry2x32(
    uint32_t k0, uint32_t k1, uint32_t x0, uint32_t x1,
    uint32_t* y0, uint32_t* y1)
{
    uint32_t k2 = k0 ^ k1 ^ 0x1BD11BDAu;
    x0 += k0; x1 += k1;
#ifdef __CUDA_ARCH__
#define ROTL32(v, r) __funnelshift_l((v), (v), (r))
#else
#define ROTL32(v, r) (((v) << (r)) | ((v) >> (32 - (r))))
#endif
#define TF_RND(r) { x0 += x1; x1 = ROTL32(x1, r); x1 ^= x0; }
    TF_RND(13) TF_RND(15) TF_RND(26) TF_RND(6)   x0 += k1; x1 += k2 + 1u;
    TF_RND(17) TF_RND(29) TF_RND(16) TF_RND(24)  x0 += k2; x1 += k0 + 2u;
    TF_RND(13) TF_RND(15) TF_RND(26) TF_RND(6)   x0 += k0; x1 += k1 + 3u;
    TF_RND(17) TF_RND(29) TF_RND(16) TF_RND(24)  x0 += k1; x1 += k2 + 4u;
    TF_RND(13) TF_RND(15) TF_RND(26) TF_RND(6)   x0 += k2; x1 += k0 + 5u;
#undef TF_RND
#undef ROTL32
    *y0 = x0; *y1 = x1;
}

__device__ __forceinline__ uint32_t tf_bits32(uint32_t k0, uint32_t k1, uint32_t j) {
    uint32_t o0, o1;
    threefry2x32(k0, k1, 0u, j, &o0, &o1);
    return o0 ^ o1;
}

__device__ __forceinline__ float bits_to_u(uint32_t bits) {
    return __uint_as_float((bits >> 9) | 0x3f800000u) - 1.0f;
}
__device__ __forceinline__ float bits_to_E(uint32_t bits) {
    float u = bits_to_u(bits);
    if (u == 0.0f) u = TINY_F;
    return -__logf(u);
}

// ---------------- fused kernel ----------------
__global__ __launch_bounds__(THREADS_R, 8)
void fused_kernel(const float* __restrict__ verify,
                  const float* __restrict__ draft,
                  const int* __restrict__ ids,
                  float* __restrict__ out,
                  uint32_t ku0, uint32_t ku1,
                  uint32_t kr0, uint32_t kr1,
                  uint32_t kb0, uint32_t kb1)
{
    __shared__ float rbuf[WARPS_R][CAP];
    __shared__ int   ibuf[WARPS_R][CAP];
    __shared__ float sv[THREADS_R];
    __shared__ int   si[THREADS_R];
    __shared__ float f_su[ROWS];
    __shared__ int   f_rec[ROWS];
    __shared__ int   f_bon[B_];
    __shared__ unsigned s_rank;

    const int t    = threadIdx.x;
    const int lane = t & 31;
    const int warp = t >> 5;

    if (blockIdx.x < GRID_REC) {
        // ---- recovered: 2-half compaction ----
        const int row = blockIdx.x / SPLITS_R;      // 0..511
        const int s   = blockIdx.x % SPLITS_R;
        const long vOff = ((long)(row >> 3) * 9 + (row & 7)) * V_;
        const long dOff = (long)row * V_;
        const int v0 = s * CHUNK_R;

        const float4* vr4 = (const float4*)(verify + vOff + v0);
        const float4* dr4 = (const float4*)(draft  + dOff + v0);

        const int qbase = warp * WCHUNK4;
        const uint32_t rowbase = (uint32_t)row * (uint32_t)V_;

        float bv = -1.0f;
        int   bi = v0;

#pragma unroll
        for (int half = 0; half < 2; half++) {
            int cnt = 0;                             // warp-uniform
#pragma unroll
            for (int it2 = 0; it2 < 2; it2++) {
                int qi = (half * 2 + it2) * 32 + lane;   // 0..127
                bool valid = qi < WCHUNK4;
                int q = qbase + (valid ? qi : 0);
                float4 va = vr4[q], da = dr4[q];
                float r[4] = { va.x - da.x, va.y - da.y, va.z - da.z, va.w - da.w };
                int ebase = v0 + q * 4;
#pragma unroll
                for (int j = 0; j < 4; j++) {
                    bool pos = valid && (r[j] > 0.0f);
                    unsigned m = __ballot_sync(0xFFFFFFFFu, pos);
                    if (pos) {
                        int slot = cnt + __popc(m & ((1u << lane) - 1u));
                        rbuf[warp][slot] = r[j];
                        ibuf[warp][slot] = ebase + j;
                    }
                    cnt += __popc(m);
                }
            }
            __syncwarp();
            // drain: threefry only for compacted positives
            for (int k = lane; k < cnt; k += 32) {
                float r  = rbuf[warp][k];
                int   ix = ibuf[warp][k];
                uint32_t bits = tf_bits32(kr0, kr1, rowbase + (uint32_t)ix);
                float f = __fdividef(r, bits_to_E(bits));
                if (f > bv) { bv = f; bi = ix; }
            }
            __syncwarp();
        }

        // block argmax -> global partials
        sv[t] = bv; si[t] = bi;
        __syncthreads();
        for (int o = THREADS_R >> 1; o > 0; o >>= 1) {
            if (t < o) {
                float v2 = sv[t + o]; int i2 = si[t + o];
                if (v2 > sv[t] || (v2 == sv[t] && i2 < si[t])) { sv[t] = v2; si[t] = i2; }
            }
            __syncthreads();
        }
        if (t == 0) {
            g_rval[row * SPLITS_R + s] = sv[0];
            g_ridx[row * SPLITS_R + s] = si[0];
        }
    } else {
        // ---- bonus: all elements need RNG ----
        const int bid = blockIdx.x - GRID_REC;
        const int b = bid / SPLITS_B;               // 0..63
        const int s = bid % SPLITS_B;
        const long vOff = ((long)b * 9 + 8) * V_;

        const int chunk = V_ / SPLITS_B;            // 8000
        const int v0 = s * chunk;
        const float4* p4 = (const float4*)(verify + vOff + v0);

        float bv = -1.0f;
        int   bi = v0;

        const int n4 = chunk / 4;                   // 2000
        for (int q = t; q < n4; q += THREADS_R) {
            float4 pa = p4[q];
            int vbase = v0 + q * 4;
            uint32_t cbase = (uint32_t)b * (uint32_t)V_ + (uint32_t)vbase;
            float f[4] = { pa.x, pa.y, pa.z, pa.w };
#pragma unroll
            for (int j = 0; j < 4; j++) {
                uint32_t bits = tf_bits32(kb0, kb1, cbase + j);
                float sc = __fdividef(f[j], bits_to_E(bits));
                if (sc > bv) { bv = sc; bi = vbase + j; }
            }
        }

        sv[t] = bv; si[t] = bi;
        __syncthreads();
        for (int o = THREADS_R >> 1; o > 0; o >>= 1) {
            if (t < o) {
                float v2 = sv[t + o]; int i2 = si[t + o];
                if (v2 > sv[t] || (v2 == sv[t] && i2 < si[t])) { sv[t] = v2; si[t] = i2; }
            }
            __syncthreads();
        }
        if (t == 0) {
            g_bval[b * SPLITS_B + s] = sv[0];
            g_bidx[b * SPLITS_B + s] = si[0];
        }
    }

    // ---- last-block finalize ----
    __threadfence();
    if (t == 0) s_rank = atomicAdd(&g_done, 1u);
    __syncthreads();
    if (s_rank != GRID_TOT - 1) return;

    // accept uniforms (2 per thread)
    for (int i = t; i < ROWS; i += THREADS_R)
        f_su[i] = bits_to_u(tf_bits32(ku0, ku1, (uint32_t)i));

    // reduce recovered partials (2 rows per thread)
    for (int row = t; row < ROWS; row += THREADS_R) {
        float bv = -2.0f; int bi = 0;
        for (int s = 0; s < SPLITS_R; s++) {
            float v = g_rval[row * SPLITS_R + s];
            int   i = g_ridx[row * SPLITS_R + s];
            if (v > bv || (v == bv && i < bi)) { bv = v; bi = i; }
        }
        f_rec[row] = bi;
    }
    if (t < B_) {
        float bv = -2.0f; int bi = 0;
        for (int s = 0; s < SPLITS_B; s++) {
            float v = g_bval[t * SPLITS_B + s];
            int   i = g_bidx[t * SPLITS_B + s];
            if (v > bv || (v == bv && i < bi)) { bv = v; bi = i; }
        }
        f_bon[t] = bi;
    }
    __syncthreads();

    if (t < B_) {
        const int b = t;
        int acc = 0, emitted = 0;
        bool chain = true;
        for (int n = 0; n < N_; n++) {
            int idx = b * N_ + n;
            int tok = ids[idx];
            float p = verify[((long)b * 9 + n) * V_ + tok];
            float q = draft[(long)idx * V_ + tok];
            float u = f_su[idx];
            bool a = __fmul_rn(u, q) < p;
            acc += a ? 1 : 0;
            if (chain) { if (a) emitted++; else chain = false; }
        }
        int final_tok = (emitted < N_) ? f_rec[b * N_ + emitted] : f_bon[b];
        for (int i = 0; i <= N_; i++) {
            float val;
            if (i < emitted)       val = (float)ids[b * N_ + i];
            else if (i == emitted) val = (float)final_tok;
            else                   val = -1.0f;
            out[b * (N_ + 1) + i] = val;
        }
        out[B_ * (N_ + 1) + b]       = (float)acc;      // accepted_token_num
        out[B_ * (N_ + 1) + B_ + b]  = (float)emitted;  // emitted_token_num
    }

    // reset for next graph replay
    if (t == 0) g_done = 0;
}

// ---------------- host launch ----------------
extern "C" void kernel_launch(void* const* d_in, const int* in_sizes, int n_in,
                              void* d_out, int out_size)
{
    // Bind inputs BY ELEMENT COUNT:
    const int*   draft_ids = nullptr;
    const float* draft_p   = nullptr;
    const float* verify_p  = nullptr;
    for (int i = 0; i < n_in; i++) {
        long sz = in_sizes[i];
        if (sz == (long)ROWS)                 draft_ids = (const int*)d_in[i];
        else if (sz == (long)B_ * N_ * V_)    draft_p   = (const float*)d_in[i];
        else if (sz == (long)B_ * 9 * V_)     verify_p  = (const float*)d_in[i];
    }
    float* out = (float*)d_out;

    // key(1) = (0, 1); split(key, 3) fold-like (partitionable)
    uint32_t ku0, ku1, kr0, kr1, kb0, kb1;
    threefry2x32(0u, 1u, 0u, 0u, &ku0, &ku1);
    threefry2x32(0u, 1u, 0u, 1u, &kr0, &kr1);
    threefry2x32(0u, 1u, 0u, 2u, &kb0, &kb1);

    fused_kernel<<<GRID_TOT, THREADS_R>>>(
        verify_p, draft_p, draft_ids, out, ku0, ku1, kr0, kr1, kb0, kb1);
}

// round 8
// speedup vs baseline: 1.4200x; 1.0711x over previous
#include <cuda_runtime.h>
#include <cstdint>

// ---------------------------------------------------------------------------
// RejectionSampler: chain speculative sampling, flashinfer-style.
// JAX threefry2x32 PARTITIONABLE streams (bit-exact, verified rel_err=0.0):
//   split(key,3):  key_i = threefry2x32(key, 0, i)
//   random_bits32: bits_j = o0 ^ o1 of threefry2x32(key, 0, j)
// argmax(log(x+EPS)+gumbel) computed as argmax x / (-log u)  (monotone).
// R8: alu-pipe overhead trim.
//   - SPLITS_R=25 -> 160 float4/warp = 5 exact warp-iterations (no predicates)
//   - drain-per-iteration compaction, packed uint2 entries (STS.64/LDS.64)
//   - shuffle-butterfly argmax (no smem barrier tree)
//   - last-block finalize fusion kept
// Output FLOAT32: [ (B,N+1) tokens | (B,) accepted | (B,) emitted ]
// ---------------------------------------------------------------------------

#define B_  64
#define N_  8
#define V_  128000
#define ROWS (B_ * N_)              // 512
#define SPLITS_R 25
#define SPLITS_B 16
#define THREADS_R 256
#define WARPS_R (THREADS_R / 32)    // 8
#define CHUNK_R (V_ / SPLITS_R)     // 5120 elements per block
#define WCHUNK4 ((CHUNK_R / WARPS_R) / 4) // 160 float4 per warp
#define WITERS  (WCHUNK4 / 32)      // 5 exact iterations
#define GRID_REC (ROWS * SPLITS_R)  // 12800
#define GRID_BON (B_ * SPLITS_B)    // 1024
#define GRID_TOT (GRID_REC + GRID_BON)
#define CAP 128                     // per-warp per-iteration buffer (max 128 pos)
#define TINY_F 1.17549435e-38f

// scratch (no allocations allowed)
__device__ float g_rval[ROWS * SPLITS_R];
__device__ int   g_ridx[ROWS * SPLITS_R];
__device__ float g_bval[B_ * SPLITS_B];
__device__ int   g_bidx[B_ * SPLITS_B];
__device__ unsigned g_done = 0;

// ---------------- threefry2x32 (JAX-compatible) ----------------
__host__ __device__ __forceinline__ void threefry2x32(
    uint32_t k0, uint32_t k1, uint32_t x0, uint32_t x1,
    uint32_t* y0, uint32_t* y1)
{
    uint32_t k2 = k0 ^ k1 ^ 0x1BD11BDAu;
    x0 += k0; x1 += k1;
#ifdef __CUDA_ARCH__
#define ROTL32(v, r) __funnelshift_l((v), (v), (r))
#else
#define ROTL32(v, r) (((v) << (r)) | ((v) >> (32 - (r))))
#endif
#define TF_RND(r) { x0 += x1; x1 = ROTL32(x1, r); x1 ^= x0; }
    TF_RND(13) TF_RND(15) TF_RND(26) TF_RND(6)   x0 += k1; x1 += k2 + 1u;
    TF_RND(17) TF_RND(29) TF_RND(16) TF_RND(24)  x0 += k2; x1 += k0 + 2u;
    TF_RND(13) TF_RND(15) TF_RND(26) TF_RND(6)   x0 += k0; x1 += k1 + 3u;
    TF_RND(17) TF_RND(29) TF_RND(16) TF_RND(24)  x0 += k1; x1 += k2 + 4u;
    TF_RND(13) TF_RND(15) TF_RND(26) TF_RND(6)   x0 += k2; x1 += k0 + 5u;
#undef TF_RND
#undef ROTL32
    *y0 = x0; *y1 = x1;
}

__device__ __forceinline__ uint32_t tf_bits32(uint32_t k0, uint32_t k1, uint32_t j) {
    uint32_t o0, o1;
    threefry2x32(k0, k1, 0u, j, &o0, &o1);
    return o0 ^ o1;
}

__device__ __forceinline__ float bits_to_u(uint32_t bits) {
    return __uint_as_float((bits >> 9) | 0x3f800000u) - 1.0f;
}
__device__ __forceinline__ float bits_to_E(uint32_t bits) {
    float u = bits_to_u(bits);
    if (u == 0.0f) u = TINY_F;
    return -__logf(u);
}

// warp-wide argmax butterfly (max value, min index on tie); all lanes get result
__device__ __forceinline__ void warp_argmax(float& bv, int& bi) {
#pragma unroll
    for (int o = 16; o > 0; o >>= 1) {
        float v2 = __shfl_xor_sync(0xFFFFFFFFu, bv, o);
        int   i2 = __shfl_xor_sync(0xFFFFFFFFu, bi, o);
        if (v2 > bv || (v2 == bv && i2 < bi)) { bv = v2; bi = i2; }
    }
}

// ---------------- fused kernel ----------------
__global__ __launch_bounds__(THREADS_R, 8)
void fused_kernel(const float* __restrict__ verify,
                  const float* __restrict__ draft,
                  const int* __restrict__ ids,
                  float* __restrict__ out,
                  uint32_t ku0, uint32_t ku1,
                  uint32_t kr0, uint32_t kr1,
                  uint32_t kb0, uint32_t kb1)
{
    __shared__ uint2 ebuf[WARPS_R][CAP];    // packed (value bits, index)
    __shared__ float swv[WARPS_R];
    __shared__ int   swi[WARPS_R];
    __shared__ float f_su[ROWS];
    __shared__ int   f_rec[ROWS];
    __shared__ int   f_bon[B_];
    __shared__ unsigned s_rank;

    const int t    = threadIdx.x;
    const int lane = t & 31;
    const int warp = t >> 5;

    float bv = -1.0f;
    int   bi = 0;

    if (blockIdx.x < GRID_REC) {
        // ---- recovered: compaction, drain each iteration ----
        const int row = blockIdx.x / SPLITS_R;      // 0..511
        const int s   = blockIdx.x % SPLITS_R;
        const long vOff = ((long)(row >> 3) * 9 + (row & 7)) * V_;
        const long dOff = (long)row * V_;
        const int v0 = s * CHUNK_R;

        const float4* vr4 = (const float4*)(verify + vOff + v0);
        const float4* dr4 = (const float4*)(draft  + dOff + v0);

        const int qbase = warp * WCHUNK4;
        const uint32_t rowbase = (uint32_t)row * (uint32_t)V_;
        bi = v0;

#pragma unroll
        for (int it = 0; it < WITERS; it++) {
            int q = qbase + it * 32 + lane;         // always in range
            float4 va = vr4[q], da = dr4[q];
            float r[4] = { va.x - da.x, va.y - da.y, va.z - da.z, va.w - da.w };
            int ebase = v0 + q * 4;
            int cnt = 0;                             // warp-uniform
#pragma unroll
            for (int j = 0; j < 4; j++) {
                bool pos = r[j] > 0.0f;
                unsigned m = __ballot_sync(0xFFFFFFFFu, pos);
                if (pos) {
                    int slot = cnt + __popc(m & ((1u << lane) - 1u));
                    ebuf[warp][slot] = make_uint2(__float_as_uint(r[j]),
                                                  (uint32_t)(ebase + j));
                }
                cnt += __popc(m);
            }
            __syncwarp();
            // drain: threefry only for compacted positives
            for (int k = lane; k < cnt; k += 32) {
                uint2 e = ebuf[warp][k];
                float r_  = __uint_as_float(e.x);
                int   ix  = (int)e.y;
                uint32_t bits = tf_bits32(kr0, kr1, rowbase + e.y);
                float f = __fdividef(r_, bits_to_E(bits));
                if (f > bv) { bv = f; bi = ix; }
            }
            __syncwarp();
        }

        warp_argmax(bv, bi);
        if (lane == 0) { swv[warp] = bv; swi[warp] = bi; }
        __syncthreads();
        if (warp == 0) {
            float v = (lane < WARPS_R) ? swv[lane] : -2.0f;
            int   i = (lane < WARPS_R) ? swi[lane] : 0x7FFFFFFF;
            warp_argmax(v, i);
            if (lane == 0) {
                g_rval[row * SPLITS_R + s] = v;
                g_ridx[row * SPLITS_R + s] = i;
            }
        }
    } else {
        // ---- bonus: all elements need RNG ----
        const int bid = blockIdx.x - GRID_REC;
        const int b = bid / SPLITS_B;               // 0..63
        const int s = bid % SPLITS_B;
        const long vOff = ((long)b * 9 + 8) * V_;

        const int chunk = V_ / SPLITS_B;            // 8000
        const int v0 = s * chunk;
        const float4* p4 = (const float4*)(verify + vOff + v0);
        bi = v0;

        const int n4 = chunk / 4;                   // 2000
        for (int q = t; q < n4; q += THREADS_R) {
            float4 pa = p4[q];
            int vbase = v0 + q * 4;
            uint32_t cbase = (uint32_t)b * (uint32_t)V_ + (uint32_t)vbase;
            float f[4] = { pa.x, pa.y, pa.z, pa.w };
#pragma unroll
            for (int j = 0; j < 4; j++) {
                uint32_t bits = tf_bits32(kb0, kb1, cbase + j);
                float sc = __fdividef(f[j], bits_to_E(bits));
                if (sc > bv) { bv = sc; bi = vbase + j; }
            }
        }

        warp_argmax(bv, bi);
        if (lane == 0) { swv[warp] = bv; swi[warp] = bi; }
        __syncthreads();
        if (warp == 0) {
            float v = (lane < WARPS_R) ? swv[lane] : -2.0f;
            int   i = (lane < WARPS_R) ? swi[lane] : 0x7FFFFFFF;
            warp_argmax(v, i);
            if (lane == 0) {
                g_bval[b * SPLITS_B + s] = v;
                g_bidx[b * SPLITS_B + s] = i;
            }
        }
    }

    // ---- last-block finalize ----
    __threadfence();
    if (t == 0) s_rank = atomicAdd(&g_done, 1u);
    __syncthreads();
    if (s_rank != GRID_TOT - 1) return;

    for (int i = t; i < ROWS; i += THREADS_R)
        f_su[i] = bits_to_u(tf_bits32(ku0, ku1, (uint32_t)i));

    for (int row = t; row < ROWS; row += THREADS_R) {
        float mv = -2.0f; int mi = 0;
        for (int s = 0; s < SPLITS_R; s++) {
            float v = g_rval[row * SPLITS_R + s];
            int   i = g_ridx[row * SPLITS_R + s];
            if (v > mv || (v == mv && i < mi)) { mv = v; mi = i; }
        }
        f_rec[row] = mi;
    }
    if (t < B_) {
        float mv = -2.0f; int mi = 0;
        for (int s = 0; s < SPLITS_B; s++) {
            float v = g_bval[t * SPLITS_B + s];
            int   i = g_bidx[t * SPLITS_B + s];
            if (v > mv || (v == mv && i < mi)) { mv = v; mi = i; }
        }
        f_bon[t] = mi;
    }
    __syncthreads();

    if (t < B_) {
        const int b = t;
        int acc = 0, emitted = 0;
        bool chain = true;
        for (int n = 0; n < N_; n++) {
            int idx = b * N_ + n;
            int tok = ids[idx];
            float p = verify[((long)b * 9 + n) * V_ + tok];
            float q = draft[(long)idx * V_ + tok];
            float u = f_su[idx];
            bool a = __fmul_rn(u, q) < p;
            acc += a ? 1 : 0;
            if (chain) { if (a) emitted++; else chain = false; }
        }
        int final_tok = (emitted < N_) ? f_rec[b * N_ + emitted] : f_bon[b];
        for (int i = 0; i <= N_; i++) {
            float val;
            if (i < emitted)       val = (float)ids[b * N_ + i];
            else if (i == emitted) val = (float)final_tok;
            else                   val = -1.0f;
            out[b * (N_ + 1) + i] = val;
        }
        out[B_ * (N_ + 1) + b]       = (float)acc;      // accepted_token_num
        out[B_ * (N_ + 1) + B_ + b]  = (float)emitted;  // emitted_token_num
    }

    // reset for next graph replay
    if (t == 0) g_done = 0;
}

// ---------------- host launch ----------------
extern "C" void kernel_launch(void* const* d_in, const int* in_sizes, int n_in,
                              void* d_out, int out_size)
{
    // Bind inputs BY ELEMENT COUNT:
    const int*   draft_ids = nullptr;
    const float* draft_p   = nullptr;
    const float* verify_p  = nullptr;
    for (int i = 0; i < n_in; i++) {
        long sz = in_sizes[i];
        if (sz == (long)ROWS)                 draft_ids = (const int*)d_in[i];
        else if (sz == (long)B_ * N_ * V_)    draft_p   = (const float*)d_in[i];
        else if (sz == (long)B_ * 9 * V_)     verify_p  = (const float*)d_in[i];
    }
    float* out = (float*)d_out;

    // key(1) = (0, 1); split(key, 3) fold-like (partitionable)
    uint32_t ku0, ku1, kr0, kr1, kb0, kb1;
    threefry2x32(0u, 1u, 0u, 0u, &ku0, &ku1);
    threefry2x32(0u, 1u, 0u, 1u, &kr0, &kr1);
    threefry2x32(0u, 1u, 0u, 2u, &kb0, &kb1);

    fused_kernel<<<GRID_TOT, THREADS_R>>>(
        verify_p, draft_p, draft_ids, out, ku0, ku1, kr0, kr1, kb0, kb1);
}

// round 9
// speedup vs baseline: 1.4252x; 1.0036x over previous
#include <cuda_runtime.h>
#include <cstdint>

// ---------------------------------------------------------------------------
// RejectionSampler: chain speculative sampling, flashinfer-style.
// JAX threefry2x32 PARTITIONABLE streams (bit-exact, verified rel_err=0.0):
//   split(key,3):  key_i = threefry2x32(key, 0, i)
//   random_bits32: bits_j = o0 ^ o1 of threefry2x32(key, 0, j)
// argmax(log(x+EPS)+gumbel) computed as argmax x / (-log u)  (monotone).
// R9: threefry rotate via IMAD.WIDE (v * 2^r -> lo|hi) + fused LOP3
//     moves ~half the alu-pipe work onto the idle fma pipe.
//     (alu was 77.7% = binding; fma 26.4% idle)
// Output FLOAT32: [ (B,N+1) tokens | (B,) accepted | (B,) emitted ]
// ---------------------------------------------------------------------------

#define B_  64
#define N_  8
#define V_  128000
#define ROWS (B_ * N_)              // 512
#define SPLITS_R 25
#define SPLITS_B 16
#define THREADS_R 256
#define WARPS_R (THREADS_R / 32)    // 8
#define CHUNK_R (V_ / SPLITS_R)     // 5120 elements per block
#define WCHUNK4 ((CHUNK_R / WARPS_R) / 4) // 160 float4 per warp
#define WITERS  (WCHUNK4 / 32)      // 5 exact iterations
#define GRID_REC (ROWS * SPLITS_R)  // 12800
#define GRID_BON (B_ * SPLITS_B)    // 1024
#define GRID_TOT (GRID_REC + GRID_BON)
#define CAP 128                     // per-warp per-iteration buffer
#define TINY_F 1.17549435e-38f

// scratch (no allocations allowed)
__device__ float g_rval[ROWS * SPLITS_R];
__device__ int   g_ridx[ROWS * SPLITS_R];
__device__ float g_bval[B_ * SPLITS_B];
__device__ int   g_bidx[B_ * SPLITS_B];
__device__ unsigned g_done = 0;

// ---------------- threefry2x32 (JAX-compatible) ----------------
// Device rounds use rotate-by-multiply: rotl(v,r) = lo|hi of (u64)v * 2^r.
// IMAD.WIDE goes to the fma pipe; the (lo|hi)^x0 fuses into one LOP3 (alu).
__device__ __forceinline__ void threefry2x32_dev(
    uint32_t k0, uint32_t k1, uint32_t x0, uint32_t x1,
    uint32_t* y0, uint32_t* y1)
{
    uint32_t k2 = k0 ^ k1 ^ 0x1BD11BDAu;
    x0 += k0; x1 += k1;
#define TF_RND(r) { x0 += x1; \
    unsigned long long w = (unsigned long long)x1 * (1ull << (r)); \
    x1 = ((uint32_t)w | (uint32_t)(w >> 32)) ^ x0; }
    TF_RND(13) TF_RND(15) TF_RND(26) TF_RND(6)   x0 += k1; x1 += k2 + 1u;
    TF_RND(17) TF_RND(29) TF_RND(16) TF_RND(24)  x0 += k2; x1 += k0 + 2u;
    TF_RND(13) TF_RND(15) TF_RND(26) TF_RND(6)   x0 += k0; x1 += k1 + 3u;
    TF_RND(17) TF_RND(29) TF_RND(16) TF_RND(24)  x0 += k1; x1 += k2 + 4u;
    TF_RND(13) TF_RND(15) TF_RND(26) TF_RND(6)   x0 += k2; x1 += k0 + 5u;
#undef TF_RND
    *y0 = x0; *y1 = x1;
}

// host copy (plain shifts)
__host__ __device__ inline void threefry2x32_host(
    uint32_t k0, uint32_t k1, uint32_t x0, uint32_t x1,
    uint32_t* y0, uint32_t* y1)
{
    uint32_t k2 = k0 ^ k1 ^ 0x1BD11BDAu;
    x0 += k0; x1 += k1;
#define ROTL32(v, r) (((v) << (r)) | ((v) >> (32 - (r))))
#define TF_RND(r) { x0 += x1; x1 = ROTL32(x1, r); x1 ^= x0; }
    TF_RND(13) TF_RND(15) TF_RND(26) TF_RND(6)   x0 += k1; x1 += k2 + 1u;
    TF_RND(17) TF_RND(29) TF_RND(16) TF_RND(24)  x0 += k2; x1 += k0 + 2u;
    TF_RND(13) TF_RND(15) TF_RND(26) TF_RND(6)   x0 += k0; x1 += k1 + 3u;
    TF_RND(17) TF_RND(29) TF_RND(16) TF_RND(24)  x0 += k1; x1 += k2 + 4u;
    TF_RND(13) TF_RND(15) TF_RND(26) TF_RND(6)   x0 += k2; x1 += k0 + 5u;
#undef TF_RND
#undef ROTL32
    *y0 = x0; *y1 = x1;
}

__device__ __forceinline__ uint32_t tf_bits32(uint32_t k0, uint32_t k1, uint32_t j) {
    uint32_t o0, o1;
    threefry2x32_dev(k0, k1, 0u, j, &o0, &o1);
    return o0 ^ o1;
}

__device__ __forceinline__ float bits_to_u(uint32_t bits) {
    return __uint_as_float((bits >> 9) | 0x3f800000u) - 1.0f;
}
__device__ __forceinline__ float bits_to_E(uint32_t bits) {
    float u = bits_to_u(bits);
    if (u == 0.0f) u = TINY_F;
    return -__logf(u);
}

// warp-wide argmax butterfly (max value, min index on tie)
__device__ __forceinline__ void warp_argmax(float& bv, int& bi) {
#pragma unroll
    for (int o = 16; o > 0; o >>= 1) {
        float v2 = __shfl_xor_sync(0xFFFFFFFFu, bv, o);
        int   i2 = __shfl_xor_sync(0xFFFFFFFFu, bi, o);
        if (v2 > bv || (v2 == bv && i2 < bi)) { bv = v2; bi = i2; }
    }
}

// ---------------- fused kernel ----------------
__global__ __launch_bounds__(THREADS_R, 8)
void fused_kernel(const float* __restrict__ verify,
                  const float* __restrict__ draft,
                  const int* __restrict__ ids,
                  float* __restrict__ out,
                  uint32_t ku0, uint32_t ku1,
                  uint32_t kr0, uint32_t kr1,
                  uint32_t kb0, uint32_t kb1)
{
    __shared__ uint2 ebuf[WARPS_R][CAP];    // packed (value bits, index)
    __shared__ float swv[WARPS_R];
    __shared__ int   swi[WARPS_R];
    __shared__ float f_su[ROWS];
    __shared__ int   f_rec[ROWS];
    __shared__ int   f_bon[B_];
    __shared__ unsigned s_rank;

    const int t    = threadIdx.x;
    const int lane = t & 31;
    const int warp = t >> 5;

    float bv = -1.0f;
    int   bi = 0;

    if (blockIdx.x < GRID_REC) {
        // ---- recovered: compaction, drain each iteration ----
        const int row = blockIdx.x / SPLITS_R;      // 0..511
        const int s   = blockIdx.x % SPLITS_R;
        const long vOff = ((long)(row >> 3) * 9 + (row & 7)) * V_;
        const long dOff = (long)row * V_;
        const int v0 = s * CHUNK_R;

        const float4* vr4 = (const float4*)(verify + vOff + v0);
        const float4* dr4 = (const float4*)(draft  + dOff + v0);

        const int qbase = warp * WCHUNK4;
        const uint32_t rowbase = (uint32_t)row * (uint32_t)V_;
        bi = v0;

#pragma unroll
        for (int it = 0; it < WITERS; it++) {
            int q = qbase + it * 32 + lane;         // always in range
            float4 va = vr4[q], da = dr4[q];
            float r[4] = { va.x - da.x, va.y - da.y, va.z - da.z, va.w - da.w };
            int ebase = v0 + q * 4;
            int cnt = 0;                             // warp-uniform
#pragma unroll
            for (int j = 0; j < 4; j++) {
                bool pos = r[j] > 0.0f;
                unsigned m = __ballot_sync(0xFFFFFFFFu, pos);
                if (pos) {
                    int slot = cnt + __popc(m & ((1u << lane) - 1u));
                    ebuf[warp][slot] = make_uint2(__float_as_uint(r[j]),
                                                  (uint32_t)(ebase + j));
                }
                cnt += __popc(m);
            }
            __syncwarp();
            // drain: threefry only for compacted positives
            for (int k = lane; k < cnt; k += 32) {
                uint2 e = ebuf[warp][k];
                float r_  = __uint_as_float(e.x);
                int   ix  = (int)e.y;
                uint32_t bits = tf_bits32(kr0, kr1, rowbase + e.y);
                float f = __fdividef(r_, bits_to_E(bits));
                if (f > bv) { bv = f; bi = ix; }
            }
            __syncwarp();
        }

        warp_argmax(bv, bi);
        if (lane == 0) { swv[warp] = bv; swi[warp] = bi; }
        __syncthreads();
        if (warp == 0) {
            float v = (lane < WARPS_R) ? swv[lane] : -2.0f;
            int   i = (lane < WARPS_R) ? swi[lane] : 0x7FFFFFFF;
            warp_argmax(v, i);
            if (lane == 0) {
                g_rval[row * SPLITS_R + s] = v;
                g_ridx[row * SPLITS_R + s] = i;
            }
        }
    } else {
        // ---- bonus: all elements need RNG ----
        const int bid = blockIdx.x - GRID_REC;
        const int b = bid / SPLITS_B;               // 0..63
        const int s = bid % SPLITS_B;
        const long vOff = ((long)b * 9 + 8) * V_;

        const int chunk = V_ / SPLITS_B;            // 8000
        const int v0 = s * chunk;
        const float4* p4 = (const float4*)(verify + vOff + v0);
        bi = v0;

        const int n4 = chunk / 4;                   // 2000
        for (int q = t; q < n4; q += THREADS_R) {
            float4 pa = p4[q];
            int vbase = v0 + q * 4;
            uint32_t cbase = (uint32_t)b * (uint32_t)V_ + (uint32_t)vbase;
            float f[4] = { pa.x, pa.y, pa.z, pa.w };
#pragma unroll
            for (int j = 0; j < 4; j++) {
                uint32_t bits = tf_bits32(kb0, kb1, cbase + j);
                float sc = __fdividef(f[j], bits_to_E(bits));
                if (sc > bv) { bv = sc; bi = vbase + j; }
            }
        }

        warp_argmax(bv, bi);
        if (lane == 0) { swv[warp] = bv; swi[warp] = bi; }
        __syncthreads();
        if (warp == 0) {
            float v = (lane < WARPS_R) ? swv[lane] : -2.0f;
            int   i = (lane < WARPS_R) ? swi[lane] : 0x7FFFFFFF;
            warp_argmax(v, i);
            if (lane == 0) {
                g_bval[b * SPLITS_B + s] = v;
                g_bidx[b * SPLITS_B + s] = i;
            }
        }
    }

    // ---- last-block finalize ----
    __threadfence();
    if (t == 0) s_rank = atomicAdd(&g_done, 1u);
    __syncthreads();
    if (s_rank != GRID_TOT - 1) return;

    for (int i = t; i < ROWS; i += THREADS_R)
        f_su[i] = bits_to_u(tf_bits32(ku0, ku1, (uint32_t)i));

    for (int row = t; row < ROWS; row += THREADS_R) {
        float mv = -2.0f; int mi = 0;
        for (int s = 0; s < SPLITS_R; s++) {
            float v = g_rval[row * SPLITS_R + s];
            int   i = g_ridx[row * SPLITS_R + s];
            if (v > mv || (v == mv && i < mi)) { mv = v; mi = i; }
        }
        f_rec[row] = mi;
    }
    if (t < B_) {
        float mv = -2.0f; int mi = 0;
        for (int s = 0; s < SPLITS_B; s++) {
            float v = g_bval[t * SPLITS_B + s];
            int   i = g_bidx[t * SPLITS_B + s];
            if (v > mv || (v == mv && i < mi)) { mv = v; mi = i; }
        }
        f_bon[t] = mi;
    }
    __syncthreads();

    if (t < B_) {
        const int b = t;
        int acc = 0, emitted = 0;
        bool chain = true;
        for (int n = 0; n < N_; n++) {
            int idx = b * N_ + n;
            int tok = ids[idx];
            float p = verify[((long)b * 9 + n) * V_ + tok];
            float q = draft[(long)idx * V_ + tok];
            float u = f_su[idx];
            bool a = __fmul_rn(u, q) < p;
            acc += a ? 1 : 0;
            if (chain) { if (a) emitted++; else chain = false; }
        }
        int final_tok = (emitted < N_) ? f_rec[b * N_ + emitted] : f_bon[b];
        for (int i = 0; i <= N_; i++) {
            float val;
            if (i < emitted)       val = (float)ids[b * N_ + i];
            else if (i == emitted) val = (float)final_tok;
            else                   val = -1.0f;
            out[b * (N_ + 1) + i] = val;
        }
        out[B_ * (N_ + 1) + b]       = (float)acc;      // accepted_token_num
        out[B_ * (N_ + 1) + B_ + b]  = (float)emitted;  // emitted_token_num
    }

    // reset for next graph replay
    if (t == 0) g_done = 0;
}

// ---------------- host launch ----------------
extern "C" void kernel_launch(void* const* d_in, const int* in_sizes, int n_in,
                              void* d_out, int out_size)
{
    // Bind inputs BY ELEMENT COUNT:
    const int*   draft_ids = nullptr;
    const float* draft_p   = nullptr;
    const float* verify_p  = nullptr;
    for (int i = 0; i < n_in; i++) {
        long sz = in_sizes[i];
        if (sz == (long)ROWS)                 draft_ids = (const int*)d_in[i];
        else if (sz == (long)B_ * N_ * V_)    draft_p   = (const float*)d_in[i];
        else if (sz == (long)B_ * 9 * V_)     verify_p  = (const float*)d_in[i];
    }
    float* out = (float*)d_out;

    // key(1) = (0, 1); split(key, 3) fold-like (partitionable)
    uint32_t ku0, ku1, kr0, kr1, kb0, kb1;
    threefry2x32_host(0u, 1u, 0u, 0u, &ku0, &ku1);
    threefry2x32_host(0u, 1u, 0u, 1u, &kr0, &kr1);
    threefry2x32_host(0u, 1u, 0u, 2u, &kb0, &kb1);

    fused_kernel<<<GRID_TOT, THREADS_R>>>(
        verify_p, draft_p, draft_ids, out, ku0, ku1, kr0, kr1, kb0, kb1);
}